// round 16
// baseline (speedup 1.0000x reference)
#include <cuda_runtime.h>
#include <stdint.h>

// Problem constants (fixed by the reference).
static constexpr int P  = 16;    // permutations
static constexpr int B  = 4096;  // batch
static constexpr int NB = 256;   // float4 blocks per row (D/STEP)
static constexpr int D  = 1024;  // feature dim
static constexpr int ROWS = 4;   // batch rows staged per block

// Scratch: perm table extracted from T each call (no caching allowed).
__device__ int g_perm[P * NB];

// ---------------------------------------------------------------------------
// Kernel 1: extract the block permutation from the dense T matrices.
// T[i, 4r:4r+4, 4c:4c+4] = I  when perm_i[r] = c.
// One warp per (i, r): lanes scan c, exactly one lane finds the 1.0.
// ---------------------------------------------------------------------------
__global__ void extract_perms_kernel(const float* __restrict__ T) {
    int warp_global = (blockIdx.x * blockDim.x + threadIdx.x) >> 5;
    int lane = threadIdx.x & 31;
    if (warp_global >= P * NB) return;
    int i = warp_global >> 8;      // permutation index
    int r = warp_global & (NB - 1);
    const float* row = T + ((size_t)i * D + 4 * r) * D;  // row o = 4r of T[i]
#pragma unroll
    for (int k = 0; k < NB / 32; ++k) {
        int c = lane + 32 * k;
        if (row[4 * c] > 0.5f) g_perm[warp_global] = c;
    }
}

// ---------------------------------------------------------------------------
// Kernel 2: smem-staged shuffle, single-wave occupancy.
//   __launch_bounds__(256, 7): regs <= 36 -> 7 CTAs/SM -> all 1024 CTAs
//   resident in ONE wave (7*148 = 1036), no tail-wave stragglers.
//   Perm slice pre-permuted into smem (s_pb) so the hot loop is pure
//   LDS + LDS + coalesced __stcs STG.128 with minimal register state.
//   smem = 16KB (rows) + 16KB (s_pb) = 32KB; 7 * 32KB = 224KB <= 228KB.
// ---------------------------------------------------------------------------
__global__ void __launch_bounds__(256, 7)
permute_shuffle_kernel(const float4* __restrict__ x4,
                       const int*    __restrict__ indices,
                       float4*       __restrict__ out4) {
    __shared__ float4 s[ROWS * NB];              // 16 KB row stage
    __shared__ int    s_pb[P * NB];              // 16 KB pre-permuted perms

    const int tid = threadIdx.x;                 // column block 0..255
    const int b0  = blockIdx.x * ROWS;

    // Pre-permute the needed perm entries for every group into smem.
#pragma unroll
    for (int g = 0; g < P; ++g) {
        const int j = __ldg(&indices[g]);        // uniform, const-cached
        s_pb[g * NB + tid] = __ldg(&g_perm[j * NB + tid]);
    }

    // Stage ROWS rows of x, coalesced.
#pragma unroll
    for (int k = 0; k < ROWS; ++k)
        s[k * NB + tid] = __ldg(x4 + (size_t)(b0 + k) * NB + tid);

    __syncthreads();

    // Emit 16 permuted copies, coalesced streaming stores.
#pragma unroll 4
    for (int g = 0; g < P; ++g) {
        const int pb = s_pb[g * NB + tid];       // conflict-free LDS
        float4* dst = out4 + ((size_t)g * B + b0) * NB + tid;
#pragma unroll
        for (int k = 0; k < ROWS; ++k)
            __stcs(dst + (size_t)k * NB, s[k * NB + pb]);  // evict-first
    }
}

// ---------------------------------------------------------------------------
// Launch
// ---------------------------------------------------------------------------
extern "C" void kernel_launch(void* const* d_in, const int* in_sizes, int n_in,
                              void* d_out, int out_size) {
    const float* x   = (const float*)d_in[0];   // [B, D] fp32
    const float* T   = (const float*)d_in[1];   // [P, D, D] fp32
    const int*   idx = (const int*)d_in[2];     // [P] int32
    float* out = (float*)d_out;                 // [P*B, D] fp32

    // 1) Extract permutations: P*NB = 4096 warps -> 512 blocks x 256 threads.
    extract_perms_kernel<<<(P * NB * 32 + 255) / 256, 256>>>(T);

    // 2) Shuffle: one block per 4-row batch chunk (1024 blocks = ONE wave).
    permute_shuffle_kernel<<<B / ROWS, 256>>>(
        (const float4*)x, idx, (float4*)out);
}